// round 4
// baseline (speedup 1.0000x reference)
#include <cuda_runtime.h>
#include <math.h>

#define NB 4
#define HH 2048
#define WW 2048
#define NC 3
#define TOTAL_S (NB*NC*HH*WW)          // 50331648
#define K_RANK 25165823u               // floor(0.5*(n-1)), 0-based order stat
#define H1BITS 11
#define H1SIZE (1u<<H1BITS)            // 2048
#define H2BITS 21
#define H2SIZE (1u<<H2BITS)            // 2097152
#define H2MASK (H2SIZE-1u)

// ---------------- scratch (static device globals; no allocation) -----------
__device__ float4 g_S4[TOTAL_S/4];     // S tensor, 192 MiB, float4-aligned
__device__ unsigned g_hist1[H1SIZE];
__device__ unsigned g_hist2[H2SIZE];   // 8 MiB
__device__ unsigned g_part[1024];
__device__ unsigned g_bucket;
__device__ unsigned g_rank1;
__device__ float    g_median;

// monotone float->uint mapping (order-preserving)
__device__ __forceinline__ unsigned mono(float f){
    unsigned u = __float_as_uint(f);
    return (u & 0x80000000u) ? ~u : (u | 0x80000000u);
}

// ---------------- K0: zero the histograms ----------------------------------
__global__ void k_zero(){
    unsigned i = blockIdx.x*blockDim.x + threadIdx.x;     // 2048*1024 = 2^21 threads
    g_hist2[i] = 0u;
    if (i < H1SIZE) g_hist1[i] = 0u;
    if (i < 1024)   g_part[i]  = 0u;
    if (i == 0){ g_bucket = 0u; g_rank1 = 0u; g_median = 0.f; }
}

// ---------------- K1: Sobel + products + separable Gaussian -> S + hist1 ---
#define TY 32
#define TX 32
#define XH (TY+8)   // x tile with halo 4
#define XW (TX+8)
#define PH (TY+6)   // prod region with halo 3
#define PW (TX+6)

__global__ __launch_bounds__(256) void k_harris_S(const float* __restrict__ x,
                                                  const float* __restrict__ sobw,
                                                  const float* __restrict__ gw){
    __shared__ union ShU {
        float xs[XH][XW+1];             // 40x41
        float tm[3][PH][TX+1];          // 3x38x33 (written after xs is dead)
    } u;
    __shared__ float pr[3][PH][PW+1];   // 3x38x39
    __shared__ float gn[7];
    __shared__ float sb[18];
    __shared__ unsigned hloc[H1SIZE];

    const int tid = threadIdx.x;
    const int n  = blockIdx.z;
    const int gy0 = blockIdx.y*TY, gx0 = blockIdx.x*TX;

    for (int i = tid; i < (int)H1SIZE; i += 256) hloc[i] = 0u;
    if (tid < 18) sb[tid] = sobw[tid];
    if (tid < 7){                        // 1-D factor = row sums of normalized 2-D kernel
        float s = 0.f;
        #pragma unroll
        for (int j = 0; j < 7; j++) s += gw[tid*7 + j];
        gn[tid] = s;
    }

    const float* xn = x + (size_t)n*HH*WW;
    for (int i = tid; i < XH*XW; i += 256){
        int r = i / XW, c = i % XW;
        int gy = gy0 - 4 + r, gx = gx0 - 4 + c;
        float v = 0.f;
        if ((unsigned)gy < HH && (unsigned)gx < WW) v = xn[(size_t)gy*WW + gx];
        u.xs[r][c] = v;
    }
    __syncthreads();

    // products at halo-3 region (zero outside the image: Gaussian zero-padding)
    for (int i = tid; i < PH*PW; i += 256){
        int r = i / PW, c = i % PW;
        int gy = gy0 - 3 + r, gx = gx0 - 3 + c;
        float p0 = 0.f, p1 = 0.f, p2 = 0.f;
        if ((unsigned)gy < HH && (unsigned)gx < WW){
            float ix = 0.f, iy = 0.f;
            #pragma unroll
            for (int a = 0; a < 3; a++)
                #pragma unroll
                for (int b = 0; b < 3; b++){
                    float xv = u.xs[r+a][c+b];
                    ix += sb[a*3+b]     * xv;
                    iy += sb[9+a*3+b]   * xv;
                }
            p0 = ix*ix; p1 = iy*iy; p2 = ix*iy;
        }
        pr[0][r][c] = p0; pr[1][r][c] = p1; pr[2][r][c] = p2;
    }
    __syncthreads();

    // horizontal Gaussian (xs no longer needed; reuse as tm)
    for (int i = tid; i < 3*PH*TX; i += 256){
        int c = i / (PH*TX);
        int rem = i % (PH*TX);
        int r = rem / TX, j = rem % TX;
        float s = 0.f;
        #pragma unroll
        for (int v = 0; v < 7; v++) s += gn[v] * pr[c][r][j+v];
        u.tm[c][r][j] = s;
    }
    __syncthreads();

    // vertical Gaussian + store S + histogram
    float* gS = (float*)g_S4;
    for (int i = tid; i < 3*TY*TX; i += 256){
        int c = i / (TY*TX);
        int rem = i % (TY*TX);
        int r = rem / TX, j = rem % TX;
        float s = 0.f;
        #pragma unroll
        for (int v = 0; v < 7; v++) s += gn[v] * u.tm[c][r+v][j];
        int gy = gy0 + r, gx = gx0 + j;
        gS[(((size_t)n*NC + c)*HH + gy)*WW + gx] = s;
        atomicAdd(&hloc[mono(s) >> (32 - H1BITS)], 1u);
    }
    __syncthreads();

    for (int i = tid; i < (int)H1SIZE; i += 256){
        unsigned v = hloc[i];
        if (v) atomicAdd(&g_hist1[i], v);
    }
}

// ---------------- K2: select top-11-bit bucket -----------------------------
__global__ void k_sel1(){
    __shared__ unsigned sh[1024];
    int t = threadIdx.x;
    unsigned c0 = g_hist1[2*t], c1 = g_hist1[2*t+1];
    unsigned loc = c0 + c1;
    sh[t] = loc; __syncthreads();
    for (int st = 1; st < 1024; st <<= 1){
        unsigned v = (t >= st) ? sh[t-st] : 0u;
        __syncthreads();
        sh[t] += v;
        __syncthreads();
    }
    unsigned incl = sh[t], excl = incl - loc;
    const unsigned k = K_RANK;
    if (k >= excl && k < incl){
        if (k < excl + c0){ g_bucket = 2*t;     g_rank1 = k - excl; }
        else              { g_bucket = 2*t + 1; g_rank1 = k - excl - c0; }
    }
}

// ---------------- K3: histogram low-21 bits of in-bucket elements ----------
__global__ void k_hist2(){
    const unsigned b = g_bucket;
    const int n4 = TOTAL_S/4;
    const int stride = gridDim.x * blockDim.x;
    for (int i = blockIdx.x*blockDim.x + threadIdx.x; i < n4; i += stride){
        float4 v = g_S4[i];
        unsigned u0 = mono(v.x), u1 = mono(v.y), u2 = mono(v.z), u3 = mono(v.w);
        if ((u0 >> H2BITS) == b) atomicAdd(&g_hist2[u0 & H2MASK], 1u);
        if ((u1 >> H2BITS) == b) atomicAdd(&g_hist2[u1 & H2MASK], 1u);
        if ((u2 >> H2BITS) == b) atomicAdd(&g_hist2[u2 & H2MASK], 1u);
        if ((u3 >> H2BITS) == b) atomicAdd(&g_hist2[u3 & H2MASK], 1u);
    }
}

// ---------------- K4a: partial sums over 1024 groups of 2048 bins ----------
__global__ void k_part(){
    __shared__ unsigned red[256];
    unsigned b = blockIdx.x, t = threadIdx.x;
    unsigned s = 0;
    for (int i = t; i < 2048; i += 256) s += g_hist2[b*2048 + i];
    red[t] = s; __syncthreads();
    for (int st = 128; st > 0; st >>= 1){
        if (t < st) red[t] += red[t + st];
        __syncthreads();
    }
    if (t == 0) g_part[b] = red[0];
}

// ---------------- K4b: final select -> exact median float ------------------
__global__ void k_sel2(){
    __shared__ unsigned sh[1024];
    __shared__ unsigned sG, sR;
    int t = threadIdx.x;

    // phase 1: which group of 2048 bins
    unsigned loc = g_part[t];
    sh[t] = loc; __syncthreads();
    for (int st = 1; st < 1024; st <<= 1){
        unsigned v = (t >= st) ? sh[t-st] : 0u;
        __syncthreads();
        sh[t] += v;
        __syncthreads();
    }
    unsigned incl = sh[t], excl = incl - loc;
    unsigned r1 = g_rank1;
    if (r1 >= excl && r1 < incl){ sG = t; sR = r1 - excl; }
    __syncthreads();
    unsigned G = sG, r2 = sR;

    // phase 2: which bin within the group (2 bins / thread)
    unsigned c0 = g_hist2[G*2048 + 2*t], c1 = g_hist2[G*2048 + 2*t + 1];
    unsigned loc2 = c0 + c1;
    __syncthreads();
    sh[t] = loc2; __syncthreads();
    for (int st = 1; st < 1024; st <<= 1){
        unsigned v = (t >= st) ? sh[t-st] : 0u;
        __syncthreads();
        sh[t] += v;
        __syncthreads();
    }
    unsigned incl2 = sh[t], excl2 = incl2 - loc2;
    if (r2 >= excl2 && r2 < incl2){
        unsigned j = (r2 < excl2 + c0) ? (2*t) : (2*t + 1);
        unsigned u = (g_bucket << H2BITS) | (G*2048 + j);
        unsigned fb = (u & 0x80000000u) ? (u ^ 0x80000000u) : ~u;
        g_median = __uint_as_float(fb);
    }
}

// ---------------- K5: threshold + separable 7x7 NMS ------------------------
#define MTY 32
#define MTX 32
#define MHH (MTY+6)
#define MWW (MTX+6)

__global__ __launch_bounds__(256) void k_nms(float* __restrict__ out){
    __shared__ float xt[MHH][MWW+2];    // 38 x 40
    __shared__ float rm[MHH][MTX+1];    // 38 x 33
    const float med = g_median;
    const int nc  = blockIdx.z;         // 0..11 = (n*3+c)
    const int gy0 = blockIdx.y*MTY, gx0 = blockIdx.x*MTX;
    const float* Sp = (const float*)g_S4 + (size_t)nc*HH*WW;
    const int tid = threadIdx.x;

    for (int i = tid; i < MHH*MWW; i += 256){
        int r = i / MWW, c = i % MWW;
        int gy = gy0 - 3 + r, gx = gx0 - 3 + c;
        float v = -INFINITY;
        if ((unsigned)gy < HH && (unsigned)gx < WW){
            float s = Sp[(size_t)gy*WW + gx];
            v = (s > med) ? s : 0.f;
        }
        xt[r][c] = v;
    }
    __syncthreads();

    for (int i = tid; i < MHH*MTX; i += 256){
        int r = i / MTX, j = i % MTX;
        float m = xt[r][j];
        #pragma unroll
        for (int v = 1; v < 7; v++) m = fmaxf(m, xt[r][j+v]);
        rm[r][j] = m;
    }
    __syncthreads();

    float* op = out + (size_t)nc*HH*WW;
    for (int i = tid; i < MTY*MTX; i += 256){
        int r = i / MTX, j = i % MTX;
        float m = rm[r][j];
        #pragma unroll
        for (int v = 1; v < 7; v++) m = fmaxf(m, rm[r+v][j]);
        float xc = xt[r+3][j+3];
        op[(size_t)(gy0 + r)*WW + gx0 + j] = (xc == m) ? xc : 0.f;
    }
}

// ---------------- launcher --------------------------------------------------
extern "C" void kernel_launch(void* const* d_in, const int* in_sizes, int n_in,
                              void* d_out, int out_size){
    const float* x    = (const float*)d_in[0];   // (4,1,2048,2048)
    const float* sobw = (const float*)d_in[1];   // (2,1,3,3)
    const float* gw   = (const float*)d_in[2];   // (3,1,7,7)
    float* out = (float*)d_out;

    k_zero<<<2048, 1024>>>();                              // zero 2^21 + small
    dim3 g1(WW/TX, HH/TY, NB);
    k_harris_S<<<g1, 256>>>(x, sobw, gw);
    k_sel1<<<1, 1024>>>();
    k_hist2<<<2048, 256>>>();
    k_part<<<1024, 256>>>();
    k_sel2<<<1, 1024>>>();
    dim3 g5(WW/MTX, HH/MTY, NB*NC);
    k_nms<<<g5, 256>>>(out);
}